// round 13
// baseline (speedup 1.0000x reference)
#include <cuda_runtime.h>
#include <cuda_bf16.h>
#include <cstdint>

#define B_  32
#define T_  12
#define N_  512
#define E_  10
#define K_  3
#define CI_ 64
#define CO_ 64

// Scratch (static device globals -- allocation-free per harness rules)
__device__ float         g_diag2[T_ * N_];                    // 2 * diag(A), fp32
__device__ __nv_bfloat16 g_Ah[(size_t)T_ * N_ * N_];          // A hi (bf16)
__device__ __nv_bfloat16 g_Al[(size_t)T_ * N_ * N_];          // A lo (bf16)
__device__ __nv_bfloat16 g_xh[(size_t)B_ * T_ * N_ * CI_];    // x hi
__device__ __nv_bfloat16 g_xl[(size_t)B_ * T_ * N_ * CI_];    // x lo
__device__ float         g_xg1[(size_t)B_ * T_ * N_ * CI_];   // A@x propagated (fp32)

// ---------------------------------------------------------------------------
// Kernel 1: adjacency. Warp-per-row; block = 8 rows, emb[t] loaded once.
// ---------------------------------------------------------------------------
__global__ void __launch_bounds__(256) k_adj(const float* __restrict__ emb) {
    const int t    = blockIdx.y;
    const int wid  = threadIdx.x >> 5;
    const int lane = threadIdx.x & 31;
    const int n    = blockIdx.x * 8 + wid;

    __shared__ float se[N_ * E_];
    const float* et = emb + (size_t)t * N_ * E_;
    for (int i = threadIdx.x; i < N_ * E_; i += 256) se[i] = et[i];
    __syncthreads();

    float en[E_];
#pragma unroll
    for (int e = 0; e < E_; e++) en[e] = se[n * E_ + e];

    float v[16];
#pragma unroll
    for (int q = 0; q < 16; q++) {
        const int m = lane + 32 * q;
        float s = 0.f;
#pragma unroll
        for (int e = 0; e < E_; e++) s = fmaf(en[e], se[m * E_ + e], s);
        v[q] = fmaxf(s, 0.f);
    }

    float mx = v[0];
#pragma unroll
    for (int q = 1; q < 16; q++) mx = fmaxf(mx, v[q]);
#pragma unroll
    for (int o = 16; o > 0; o >>= 1) mx = fmaxf(mx, __shfl_xor_sync(0xffffffffu, mx, o));

    float sum = 0.f;
#pragma unroll
    for (int q = 0; q < 16; q++) {
        v[q] = expf(v[q] - mx);
        sum += v[q];
    }
#pragma unroll
    for (int o = 16; o > 0; o >>= 1) sum += __shfl_xor_sync(0xffffffffu, sum, o);
    const float inv = 1.0f / sum;

    const size_t base = ((size_t)t * N_ + n) * N_;
#pragma unroll
    for (int q = 0; q < 16; q++) {
        const float p = v[q] * inv;
        const __nv_bfloat16 h = __float2bfloat16(p);
        const __nv_bfloat16 l = __float2bfloat16(p - __bfloat162float(h));
        g_Ah[base + lane + 32 * q] = h;
        g_Al[base + lane + 32 * q] = l;
        if (q == (n >> 5) && lane == (n & 31))
            g_diag2[t * N_ + n] = 2.0f * p;
    }
}

// ---------------------------------------------------------------------------
// Kernel 1b: split x into bf16 hi/lo. 4 elems/thread, exact-size grid.
// ---------------------------------------------------------------------------
__global__ void __launch_bounds__(256) k_split(const float* __restrict__ x) {
    const size_t i = ((size_t)blockIdx.x * 256 + threadIdx.x) * 4;
    const float4 vv = *(const float4*)(x + i);
    float f[4];
    f[0] = vv.x; f[1] = vv.y; f[2] = vv.z; f[3] = vv.w;
    __nv_bfloat16 h[4], l[4];
#pragma unroll
    for (int j = 0; j < 4; j++) {
        h[j] = __float2bfloat16(f[j]);
        l[j] = __float2bfloat16(f[j] - __bfloat162float(h[j]));
    }
    *((__nv_bfloat162*)(g_xh + i))     = __halves2bfloat162(h[0], h[1]);
    *((__nv_bfloat162*)(g_xh + i + 2)) = __halves2bfloat162(h[2], h[3]);
    *((__nv_bfloat162*)(g_xl + i))     = __halves2bfloat162(l[0], l[1]);
    *((__nv_bfloat162*)(g_xl + i + 2)) = __halves2bfloat162(l[2], l[3]);
}

// ---------------------------------------------------------------------------
// mma helpers (shared by k_spmm and k_out)
// ---------------------------------------------------------------------------
__device__ __forceinline__ unsigned sptr(const void* p) {
    return (unsigned)__cvta_generic_to_shared(p);
}
__device__ __forceinline__ void ldsm4(unsigned* r, unsigned a) {
    asm volatile("ldmatrix.sync.aligned.m8n8.x4.shared.b16 {%0,%1,%2,%3}, [%4];"
                 : "=r"(r[0]), "=r"(r[1]), "=r"(r[2]), "=r"(r[3]) : "r"(a));
}
__device__ __forceinline__ void ldsm4t(unsigned* r, unsigned a) {
    asm volatile("ldmatrix.sync.aligned.m8n8.x4.trans.shared.b16 {%0,%1,%2,%3}, [%4];"
                 : "=r"(r[0]), "=r"(r[1]), "=r"(r[2]), "=r"(r[3]) : "r"(a));
}
__device__ __forceinline__ void mma16816(float* c, const unsigned* a, const unsigned* b) {
    asm volatile(
        "mma.sync.aligned.m16n8k16.row.col.f32.bf16.bf16.f32 "
        "{%0,%1,%2,%3}, {%4,%5,%6,%7}, {%8,%9}, {%0,%1,%2,%3};"
        : "+f"(c[0]), "+f"(c[1]), "+f"(c[2]), "+f"(c[3])
        : "r"(a[0]), "r"(a[1]), "r"(a[2]), "r"(a[3]), "r"(b[0]), "r"(b[1]));
}

// ---------------------------------------------------------------------------
// Kernel 2: xg1 = A @ x via mma.sync m16n8k16 bf16, 3-product split.
// ---------------------------------------------------------------------------
#define SA 40   // Ah_s row stride (bf16)
#define SX 72   // Xs row stride (bf16)

__global__ void __launch_bounds__(256) k_spmm() {
    const int bt = blockIdx.y;             // b*T + t
    const int t  = bt % T_;
    const int n0 = blockIdx.x * 128;

    __shared__ __align__(16) __nv_bfloat16 Ah_s[128 * SA];
    __shared__ __align__(16) __nv_bfloat16 Al_s[128 * SA];
    __shared__ __align__(16) __nv_bfloat16 Xh_s[32 * SX];
    __shared__ __align__(16) __nv_bfloat16 Xl_s[32 * SX];

    const int tid  = threadIdx.x;
    const int lane = tid & 31;
    const int warp = tid >> 5;
    const int wm   = (warp & 3) * 32;
    const int wn   = (warp >> 2) * 32;

    const int rA = tid >> 1;
    const int qA = (tid & 1) * 16;
    const int mX = tid >> 3;
    const int cX = (tid & 7) * 8;

    const __nv_bfloat16* gAh = g_Ah + ((size_t)t * N_ + n0 + rA) * N_;
    const __nv_bfloat16* gAl = g_Al + ((size_t)t * N_ + n0 + rA) * N_;
    const __nv_bfloat16* gXh = g_xh + ((size_t)bt * N_ + mX) * CI_ + cX;
    const __nv_bfloat16* gXl = g_xl + ((size_t)bt * N_ + mX) * CI_ + cX;

    float acc[2][4][4];
#pragma unroll
    for (int i = 0; i < 2; i++)
#pragma unroll
        for (int j = 0; j < 4; j++)
#pragma unroll
            for (int r = 0; r < 4; r++) acc[i][j][r] = 0.f;

    const int sub = lane >> 3;
    const int rl  = lane & 7;
    const int rAdd = ((sub & 1) << 3) + rl;
    const int cAdd = (sub >> 1) << 3;
    const unsigned baseAh = sptr(Ah_s);
    const unsigned baseAl = sptr(Al_s);
    const unsigned baseXh = sptr(Xh_s);
    const unsigned baseXl = sptr(Xl_s);

    uint4 pAh0, pAh1, pAl0, pAl1, pXh, pXl;

    pAh0 = *(const uint4*)(gAh + qA);
    pAh1 = *(const uint4*)(gAh + qA + 8);
    pAl0 = *(const uint4*)(gAl + qA);
    pAl1 = *(const uint4*)(gAl + qA + 8);
    pXh  = *(const uint4*)(gXh);
    pXl  = *(const uint4*)(gXl);
    *(uint4*)&Ah_s[rA * SA + qA]     = pAh0;
    *(uint4*)&Ah_s[rA * SA + qA + 8] = pAh1;
    *(uint4*)&Al_s[rA * SA + qA]     = pAl0;
    *(uint4*)&Al_s[rA * SA + qA + 8] = pAl1;
    *(uint4*)&Xh_s[mX * SX + cX]     = pXh;
    *(uint4*)&Xl_s[mX * SX + cX]     = pXl;
    __syncthreads();

    for (int c = 0; c < 16; c++) {
        if (c < 15) {
            const int m0 = (c + 1) * 32;
            pAh0 = *(const uint4*)(gAh + m0 + qA);
            pAh1 = *(const uint4*)(gAh + m0 + qA + 8);
            pAl0 = *(const uint4*)(gAl + m0 + qA);
            pAl1 = *(const uint4*)(gAl + m0 + qA + 8);
            pXh  = *(const uint4*)(gXh + (size_t)m0 * CI_);
            pXl  = *(const uint4*)(gXl + (size_t)m0 * CI_);
        }

#pragma unroll
        for (int s = 0; s < 2; s++) {
            unsigned ah[2][4], al[2][4], bh[2][4], bl[2][4];
#pragma unroll
            for (int i = 0; i < 2; i++) {
                const unsigned off =
                    (unsigned)(((wm + i * 16 + rAdd) * SA + s * 16 + cAdd) * 2);
                ldsm4(ah[i], baseAh + off);
                ldsm4(al[i], baseAl + off);
            }
#pragma unroll
            for (int jp = 0; jp < 2; jp++) {
                const unsigned off =
                    (unsigned)(((s * 16 + rAdd) * SX + wn + jp * 16 + cAdd) * 2);
                ldsm4t(bh[jp], baseXh + off);
                ldsm4t(bl[jp], baseXl + off);
            }
#pragma unroll
            for (int i = 0; i < 2; i++)
#pragma unroll
                for (int j = 0; j < 4; j++) {
                    const unsigned* bH = &bh[j >> 1][(j & 1) * 2];
                    const unsigned* bL = &bl[j >> 1][(j & 1) * 2];
                    mma16816(acc[i][j], ah[i], bH);
                    mma16816(acc[i][j], al[i], bH);
                    mma16816(acc[i][j], ah[i], bL);
                }
        }

        __syncthreads();
        if (c < 15) {
            *(uint4*)&Ah_s[rA * SA + qA]     = pAh0;
            *(uint4*)&Ah_s[rA * SA + qA + 8] = pAh1;
            *(uint4*)&Al_s[rA * SA + qA]     = pAl0;
            *(uint4*)&Al_s[rA * SA + qA + 8] = pAl1;
            *(uint4*)&Xh_s[mX * SX + cX]     = pXh;
            *(uint4*)&Xl_s[mX * SX + cX]     = pXl;
        }
        __syncthreads();
    }

    float* obase = g_xg1 + (size_t)bt * N_ * CI_;
#pragma unroll
    for (int i = 0; i < 2; i++)
#pragma unroll
        for (int j = 0; j < 4; j++) {
            const int row = n0 + wm + i * 16 + (lane >> 2);
            const int col = wn + j * 8 + (lane & 3) * 2;
            float2 lo, hi;
            lo.x = acc[i][j][0]; lo.y = acc[i][j][1];
            hi.x = acc[i][j][2]; hi.y = acc[i][j][3];
            *(float2*)(obase + (size_t)row * CI_ + col)       = lo;
            *(float2*)(obase + (size_t)(row + 8) * CI_ + col) = hi;
        }
}

// ---------------------------------------------------------------------------
// Kernel 3: fused theta-gen + output contraction on TENSOR CORES.
// Staging vectorized this round: xg stores as bf16x2 (8 STS.32/matrix),
// theta-gen restructured to (kic, o-pair) slots -> float2 W loads + bf16x2
// stores. Round-12 profile: L1=68.9% with tensor only 12% -- staging's
// narrow STS.16/LDG.32 are the L1TEX wavefront bottleneck.
// ---------------------------------------------------------------------------
#define STH 72   // theta row stride (bf16): 64 + 8
#define SXG 24   // xg row stride (bf16): 16 + 8
#define KOUT_BF16  (2 * 8 * 16 * STH + 2 * 8 * 32 * SXG)
#define KOUT_BYTES (KOUT_BF16 * 2 + (512 + 96 + 8) * 4)

__global__ void __launch_bounds__(256, 2) k_out(const float* __restrict__ x,
                                                const float* __restrict__ emb,
                                                const float* __restrict__ W,
                                                const float* __restrict__ bp,
                                                float* __restrict__ out) {
    extern __shared__ __align__(16) char smraw[];
    __nv_bfloat16* thh = (__nv_bfloat16*)smraw;        // 8*16*STH
    __nv_bfloat16* thl = thh + 8 * 16 * STH;
    __nv_bfloat16* xgh = thl + 8 * 16 * STH;           // 8*32*SXG
    __nv_bfloat16* xgl = xgh + 8 * 32 * SXG;
    float* bias_s = (float*)(xgl + 8 * 32 * SXG);      // 512
    float* emb_s  = bias_s + 512;                      // 80 (pad 96)
    float* d2_s   = emb_s + 96;                        // 8

    const int t  = blockIdx.y;
    const int n0 = blockIdx.x * 8;
    const int tid = threadIdx.x;

    if (tid < 8 * E_)
        emb_s[tid] = emb[((size_t)t * N_ + n0 + tid / E_) * E_ + (tid % E_)];
    if (tid < 8) d2_s[tid] = g_diag2[t * N_ + n0 + tid];
    __syncthreads();

    for (int ii = tid; ii < 8 * CO_; ii += 256) {
        const int nl = ii >> 6;
        const int o  = ii & 63;
        float v = 0.f;
#pragma unroll
        for (int d = 0; d < E_; d++)
            v = fmaf(emb_s[nl * E_ + d], bp[((size_t)t * E_ + d) * CO_ + o], v);
        bias_s[ii] = v;
    }

    const int lane = tid & 31;
    const int g    = tid >> 5;          // node within tile (= warp)

    const int lnl = tid >> 5;
    const int lb  = tid & 31;           // staging: thread = (node lnl, batch lb)
    const float* xrow  = x     + (((size_t)lb * T_ + t) * N_ + n0 + lnl) * CI_;
    const float* x1row = g_xg1 + (((size_t)lb * T_ + t) * N_ + n0 + lnl) * CI_;
    const float d2 = d2_s[lnl];

    // theta-gen slot: 2 slots of (kic, o-pair); kic = (tid>>5) + r*8, o0 = (tid&31)*2
    const int kicp = tid >> 5;          // 0..7
    const int o0   = (tid & 31) * 2;

    // ldmatrix per-lane sub-tile offsets (same mapping as k_spmm)
    const int sub = lane >> 3;
    const int rl  = lane & 7;
    const int rAdd = ((sub & 1) << 3) + rl;
    const int cAdd = (sub >> 1) << 3;
    const unsigned baseTh = sptr(thh);
    const unsigned baseTl = sptr(thl);
    const unsigned baseXh = sptr(xgh);
    const unsigned baseXl = sptr(xgl);

    float acc[2][8][4];
#pragma unroll
    for (int i = 0; i < 2; i++)
#pragma unroll
        for (int j = 0; j < 8; j++)
#pragma unroll
            for (int r = 0; r < 4; r++) acc[i][j][r] = 0.f;

    for (int c = 0; c < 12; c++) {
        const int k  = c >> 2;
        const int i0 = (c & 3) * 16;
        __syncthreads();

        // --- stage xg chunk as bf16 hi/lo: rows = b, cols = kic ---
        {
            float xv[16];
#pragma unroll
            for (int j4 = 0; j4 < 4; j4++) {
                float4 f;
                if (k == 0) {
                    f = *(const float4*)(xrow + i0 + j4 * 4);
                } else if (k == 1) {
                    f = *(const float4*)(x1row + i0 + j4 * 4);
                } else {
                    float4 a  = *(const float4*)(x1row + i0 + j4 * 4);
                    float4 bb = *(const float4*)(xrow + i0 + j4 * 4);
                    f.x = fmaf(d2, a.x, -bb.x);
                    f.y = fmaf(d2, a.y, -bb.y);
                    f.z = fmaf(d2, a.z, -bb.z);
                    f.w = fmaf(d2, a.w, -bb.w);
                }
                xv[j4 * 4 + 0] = f.x;
                xv[j4 * 4 + 1] = f.y;
                xv[j4 * 4 + 2] = f.z;
                xv[j4 * 4 + 3] = f.w;
            }
            __nv_bfloat16* xh_row = xgh + (lnl * 32 + lb) * SXG;
            __nv_bfloat16* xl_row = xgl + (lnl * 32 + lb) * SXG;
#pragma unroll
            for (int jj = 0; jj < 16; jj += 2) {
                const __nv_bfloat16 h0 = __float2bfloat16(xv[jj]);
                const __nv_bfloat16 h1 = __float2bfloat16(xv[jj + 1]);
                *(__nv_bfloat162*)&xh_row[jj] = __halves2bfloat162(h0, h1);
                const __nv_bfloat16 l0 =
                    __float2bfloat16(xv[jj] - __bfloat162float(h0));
                const __nv_bfloat16 l1 =
                    __float2bfloat16(xv[jj + 1] - __bfloat162float(h1));
                *(__nv_bfloat162*)&xl_row[jj] = __halves2bfloat162(l0, l1);
            }
        }

        // --- theta-gen: (kic, o-pair) slots, float2 W loads, bf16x2 stores ---
        // W index: (((t*E + d)*K + k)*CI + i)*CO + o ; d-stride = K*CI*CO
        const float* wbase = W + (((size_t)t * E_ * K_ + k) * CI_ + i0) * CO_;
#pragma unroll 1
        for (int r = 0; r < 2; r++) {
            const int kic = kicp + r * 8;
            const float* wp = wbase + kic * CO_ + o0;
            float th0[8], th1[8];
#pragma unroll
            for (int nl = 0; nl < 8; nl++) { th0[nl] = 0.f; th1[nl] = 0.f; }
#pragma unroll
            for (int d = 0; d < E_; d++) {
                const float2 wv = *(const float2*)(wp + (size_t)d * (K_ * CI_ * CO_));
#pragma unroll
                for (int nl = 0; nl < 8; nl++) {
                    const float e = emb_s[nl * E_ + d];
                    th0[nl] = fmaf(e, wv.x, th0[nl]);
                    th1[nl] = fmaf(e, wv.y, th1[nl]);
                }
            }
#pragma unroll
            for (int nl = 0; nl < 8; nl++) {
                const __nv_bfloat16 h0 = __float2bfloat16(th0[nl]);
                const __nv_bfloat16 h1 = __float2bfloat16(th1[nl]);
                *(__nv_bfloat162*)&thh[(nl * 16 + kic) * STH + o0] =
                    __halves2bfloat162(h0, h1);
                const __nv_bfloat16 l0 =
                    __float2bfloat16(th0[nl] - __bfloat162float(h0));
                const __nv_bfloat16 l1 =
                    __float2bfloat16(th1[nl] - __bfloat162float(h1));
                *(__nv_bfloat162*)&thl[(nl * 16 + kic) * STH + o0] =
                    __halves2bfloat162(l0, l1);
            }
        }
        __syncthreads();

        // --- tensor-core contraction: per warp, 32x64x16 GEMM step ---
        {
            unsigned ah[2][4], al[2][4], bh[4][4], bl[4][4];
#pragma unroll
            for (int i = 0; i < 2; i++) {
                const unsigned off =
                    (unsigned)(((g * 32 + i * 16 + rAdd) * SXG + cAdd) * 2);
                ldsm4(ah[i], baseXh + off);
                ldsm4(al[i], baseXl + off);
            }
#pragma unroll
            for (int jp = 0; jp < 4; jp++) {
                const unsigned off =
                    (unsigned)(((g * 16 + rAdd) * STH + jp * 16 + cAdd) * 2);
                ldsm4t(bh[jp], baseTh + off);
                ldsm4t(bl[jp], baseTl + off);
            }
#pragma unroll
            for (int i = 0; i < 2; i++)
#pragma unroll
                for (int j = 0; j < 8; j++) {
                    const unsigned* bH = &bh[j >> 1][(j & 1) * 2];
                    const unsigned* bL = &bl[j >> 1][(j & 1) * 2];
                    mma16816(acc[i][j], ah[i], bH);   // xh*th
                    mma16816(acc[i][j], al[i], bH);   // xl*th
                    mma16816(acc[i][j], ah[i], bL);   // xh*tl
                }
        }
    }

    // --- epilogue: relu(acc + bias) -> out[b,t,n,o] from c-fragments ---
    const int n = n0 + g;
#pragma unroll
    for (int j = 0; j < 8; j++) {
        const int col = j * 8 + (lane & 3) * 2;
        const float b0 = bias_s[g * 64 + col];
        const float b1 = bias_s[g * 64 + col + 1];
#pragma unroll
        for (int i = 0; i < 2; i++) {
            const int row0 = i * 16 + (lane >> 2);
            const int row1 = row0 + 8;
            float2 lo, hi;
            lo.x = fmaxf(acc[i][j][0] + b0, 0.f);
            lo.y = fmaxf(acc[i][j][1] + b1, 0.f);
            hi.x = fmaxf(acc[i][j][2] + b0, 0.f);
            hi.y = fmaxf(acc[i][j][3] + b1, 0.f);
            *(float2*)(out + (((size_t)row0 * T_ + t) * N_ + n) * CO_ + col) = lo;
            *(float2*)(out + (((size_t)row1 * T_ + t) * N_ + n) * CO_ + col) = hi;
        }
    }
}

extern "C" void kernel_launch(void* const* d_in, const int* in_sizes, int n_in,
                              void* d_out, int out_size) {
    const float* x   = (const float*)d_in[0];  // [B,T,N,Ci]
    const float* emb = (const float*)d_in[1];  // [T,N,E]
    const float* W   = (const float*)d_in[2];  // [T,E,K,Ci,Co]
    const float* bp  = (const float*)d_in[3];  // [T,E,Co]
    float* out = (float*)d_out;                // [B,T,N,Co]

    cudaFuncSetAttribute(k_out, cudaFuncAttributeMaxDynamicSharedMemorySize,
                         KOUT_BYTES);

    k_adj<<<dim3(N_ / 8, T_), 256>>>(emb);
    k_split<<<(B_ * T_ * N_ * CI_) / (256 * 4), 256>>>(x);
    k_spmm<<<dim3(N_ / 128, B_ * T_), 256>>>();
    k_out<<<dim3(N_ / 8, T_), 256, KOUT_BYTES>>>(x, emb, W, bp, out);
}

// round 15
// speedup vs baseline: 1.0094x; 1.0094x over previous
#include <cuda_runtime.h>
#include <cuda_bf16.h>
#include <cstdint>

#define B_  32
#define T_  12
#define N_  512
#define E_  10
#define K_  3
#define CI_ 64
#define CO_ 64

// Scratch (static device globals -- allocation-free per harness rules)
__device__ float         g_diag2[T_ * N_];                    // 2 * diag(A), fp32
__device__ __nv_bfloat16 g_Ah[(size_t)T_ * N_ * N_];          // A hi (bf16)
__device__ __nv_bfloat16 g_Al[(size_t)T_ * N_ * N_];          // A lo (bf16)
__device__ __nv_bfloat16 g_xh[(size_t)B_ * T_ * N_ * CI_];    // x hi
__device__ __nv_bfloat16 g_xl[(size_t)B_ * T_ * N_ * CI_];    // x lo
__device__ __nv_bfloat16 g_x1h[(size_t)B_ * T_ * N_ * CI_];   // xg1 hi
__device__ __nv_bfloat16 g_x1l[(size_t)B_ * T_ * N_ * CI_];   // xg1 lo
__device__ __nv_bfloat16 g_x2h[(size_t)B_ * T_ * N_ * CI_];   // xg2 hi
__device__ __nv_bfloat16 g_x2l[(size_t)B_ * T_ * N_ * CI_];   // xg2 lo

// ---------------------------------------------------------------------------
// Kernel 1: adjacency. Warp-per-row; block = 8 rows, emb[t] loaded once.
// ---------------------------------------------------------------------------
__global__ void __launch_bounds__(256) k_adj(const float* __restrict__ emb) {
    const int t    = blockIdx.y;
    const int wid  = threadIdx.x >> 5;
    const int lane = threadIdx.x & 31;
    const int n    = blockIdx.x * 8 + wid;

    __shared__ float se[N_ * E_];
    const float* et = emb + (size_t)t * N_ * E_;
    for (int i = threadIdx.x; i < N_ * E_; i += 256) se[i] = et[i];
    __syncthreads();

    float en[E_];
#pragma unroll
    for (int e = 0; e < E_; e++) en[e] = se[n * E_ + e];

    float v[16];
#pragma unroll
    for (int q = 0; q < 16; q++) {
        const int m = lane + 32 * q;
        float s = 0.f;
#pragma unroll
        for (int e = 0; e < E_; e++) s = fmaf(en[e], se[m * E_ + e], s);
        v[q] = fmaxf(s, 0.f);
    }

    float mx = v[0];
#pragma unroll
    for (int q = 1; q < 16; q++) mx = fmaxf(mx, v[q]);
#pragma unroll
    for (int o = 16; o > 0; o >>= 1) mx = fmaxf(mx, __shfl_xor_sync(0xffffffffu, mx, o));

    float sum = 0.f;
#pragma unroll
    for (int q = 0; q < 16; q++) {
        v[q] = expf(v[q] - mx);
        sum += v[q];
    }
#pragma unroll
    for (int o = 16; o > 0; o >>= 1) sum += __shfl_xor_sync(0xffffffffu, sum, o);
    const float inv = 1.0f / sum;

    const size_t base = ((size_t)t * N_ + n) * N_;
#pragma unroll
    for (int q = 0; q < 16; q++) {
        const float p = v[q] * inv;
        const __nv_bfloat16 h = __float2bfloat16(p);
        const __nv_bfloat16 l = __float2bfloat16(p - __bfloat162float(h));
        g_Ah[base + lane + 32 * q] = h;
        g_Al[base + lane + 32 * q] = l;
        if (q == (n >> 5) && lane == (n & 31))
            g_diag2[t * N_ + n] = 2.0f * p;
    }
}

// ---------------------------------------------------------------------------
// Kernel 1b: split x into bf16 hi/lo. 4 elems/thread, exact-size grid.
// ---------------------------------------------------------------------------
__global__ void __launch_bounds__(256) k_split(const float* __restrict__ x) {
    const size_t i = ((size_t)blockIdx.x * 256 + threadIdx.x) * 4;
    const float4 vv = *(const float4*)(x + i);
    float f[4];
    f[0] = vv.x; f[1] = vv.y; f[2] = vv.z; f[3] = vv.w;
    __nv_bfloat16 h[4], l[4];
#pragma unroll
    for (int j = 0; j < 4; j++) {
        h[j] = __float2bfloat16(f[j]);
        l[j] = __float2bfloat16(f[j] - __bfloat162float(h[j]));
    }
    *((__nv_bfloat162*)(g_xh + i))     = __halves2bfloat162(h[0], h[1]);
    *((__nv_bfloat162*)(g_xh + i + 2)) = __halves2bfloat162(h[2], h[3]);
    *((__nv_bfloat162*)(g_xl + i))     = __halves2bfloat162(l[0], l[1]);
    *((__nv_bfloat162*)(g_xl + i + 2)) = __halves2bfloat162(l[2], l[3]);
}

// ---------------------------------------------------------------------------
// mma helpers (shared by k_spmm and k_out)
// ---------------------------------------------------------------------------
__device__ __forceinline__ unsigned sptr(const void* p) {
    return (unsigned)__cvta_generic_to_shared(p);
}
__device__ __forceinline__ void ldsm4(unsigned* r, unsigned a) {
    asm volatile("ldmatrix.sync.aligned.m8n8.x4.shared.b16 {%0,%1,%2,%3}, [%4];"
                 : "=r"(r[0]), "=r"(r[1]), "=r"(r[2]), "=r"(r[3]) : "r"(a));
}
__device__ __forceinline__ void ldsm4t(unsigned* r, unsigned a) {
    asm volatile("ldmatrix.sync.aligned.m8n8.x4.trans.shared.b16 {%0,%1,%2,%3}, [%4];"
                 : "=r"(r[0]), "=r"(r[1]), "=r"(r[2]), "=r"(r[3]) : "r"(a));
}
__device__ __forceinline__ void mma16816(float* c, const unsigned* a, const unsigned* b) {
    asm volatile(
        "mma.sync.aligned.m16n8k16.row.col.f32.bf16.bf16.f32 "
        "{%0,%1,%2,%3}, {%4,%5,%6,%7}, {%8,%9}, {%0,%1,%2,%3};"
        : "+f"(c[0]), "+f"(c[1]), "+f"(c[2]), "+f"(c[3])
        : "r"(a[0]), "r"(a[1]), "r"(a[2]), "r"(a[3]), "r"(b[0]), "r"(b[1]));
}

// ---------------------------------------------------------------------------
// Kernel 2: xg1 = A @ x via mma.sync m16n8k16 bf16, 3-product split.
// Epilogue emits xg1 AND xg2 = d2*xg1 - x directly as bf16 hi/lo
// (x reconstructed from g_xh+g_xl, err ~2^-18), so k_out stages by pure copy.
// ---------------------------------------------------------------------------
#define SA 40   // Ah_s row stride (bf16)
#define SX 72   // Xs row stride (bf16)

__global__ void __launch_bounds__(256) k_spmm() {
    const int bt = blockIdx.y;             // b*T + t
    const int t  = bt % T_;
    const int n0 = blockIdx.x * 128;

    __shared__ __align__(16) __nv_bfloat16 Ah_s[128 * SA];
    __shared__ __align__(16) __nv_bfloat16 Al_s[128 * SA];
    __shared__ __align__(16) __nv_bfloat16 Xh_s[32 * SX];
    __shared__ __align__(16) __nv_bfloat16 Xl_s[32 * SX];

    const int tid  = threadIdx.x;
    const int lane = tid & 31;
    const int warp = tid >> 5;
    const int wm   = (warp & 3) * 32;
    const int wn   = (warp >> 2) * 32;

    const int rA = tid >> 1;
    const int qA = (tid & 1) * 16;
    const int mX = tid >> 3;
    const int cX = (tid & 7) * 8;

    const __nv_bfloat16* gAh = g_Ah + ((size_t)t * N_ + n0 + rA) * N_;
    const __nv_bfloat16* gAl = g_Al + ((size_t)t * N_ + n0 + rA) * N_;
    const __nv_bfloat16* gXh = g_xh + ((size_t)bt * N_ + mX) * CI_ + cX;
    const __nv_bfloat16* gXl = g_xl + ((size_t)bt * N_ + mX) * CI_ + cX;

    float acc[2][4][4];
#pragma unroll
    for (int i = 0; i < 2; i++)
#pragma unroll
        for (int j = 0; j < 4; j++)
#pragma unroll
            for (int r = 0; r < 4; r++) acc[i][j][r] = 0.f;

    const int sub = lane >> 3;
    const int rl  = lane & 7;
    const int rAdd = ((sub & 1) << 3) + rl;
    const int cAdd = (sub >> 1) << 3;
    const unsigned baseAh = sptr(Ah_s);
    const unsigned baseAl = sptr(Al_s);
    const unsigned baseXh = sptr(Xh_s);
    const unsigned baseXl = sptr(Xl_s);

    uint4 pAh0, pAh1, pAl0, pAl1, pXh, pXl;

    pAh0 = *(const uint4*)(gAh + qA);
    pAh1 = *(const uint4*)(gAh + qA + 8);
    pAl0 = *(const uint4*)(gAl + qA);
    pAl1 = *(const uint4*)(gAl + qA + 8);
    pXh  = *(const uint4*)(gXh);
    pXl  = *(const uint4*)(gXl);
    *(uint4*)&Ah_s[rA * SA + qA]     = pAh0;
    *(uint4*)&Ah_s[rA * SA + qA + 8] = pAh1;
    *(uint4*)&Al_s[rA * SA + qA]     = pAl0;
    *(uint4*)&Al_s[rA * SA + qA + 8] = pAl1;
    *(uint4*)&Xh_s[mX * SX + cX]     = pXh;
    *(uint4*)&Xl_s[mX * SX + cX]     = pXl;
    __syncthreads();

    for (int c = 0; c < 16; c++) {
        if (c < 15) {
            const int m0 = (c + 1) * 32;
            pAh0 = *(const uint4*)(gAh + m0 + qA);
            pAh1 = *(const uint4*)(gAh + m0 + qA + 8);
            pAl0 = *(const uint4*)(gAl + m0 + qA);
            pAl1 = *(const uint4*)(gAl + m0 + qA + 8);
            pXh  = *(const uint4*)(gXh + (size_t)m0 * CI_);
            pXl  = *(const uint4*)(gXl + (size_t)m0 * CI_);
        }

#pragma unroll
        for (int s = 0; s < 2; s++) {
            unsigned ah[2][4], al[2][4], bh[2][4], bl[2][4];
#pragma unroll
            for (int i = 0; i < 2; i++) {
                const unsigned off =
                    (unsigned)(((wm + i * 16 + rAdd) * SA + s * 16 + cAdd) * 2);
                ldsm4(ah[i], baseAh + off);
                ldsm4(al[i], baseAl + off);
            }
#pragma unroll
            for (int jp = 0; jp < 2; jp++) {
                const unsigned off =
                    (unsigned)(((s * 16 + rAdd) * SX + wn + jp * 16 + cAdd) * 2);
                ldsm4t(bh[jp], baseXh + off);
                ldsm4t(bl[jp], baseXl + off);
            }
#pragma unroll
            for (int i = 0; i < 2; i++)
#pragma unroll
                for (int j = 0; j < 4; j++) {
                    const unsigned* bH = &bh[j >> 1][(j & 1) * 2];
                    const unsigned* bL = &bl[j >> 1][(j & 1) * 2];
                    mma16816(acc[i][j], ah[i], bH);
                    mma16816(acc[i][j], al[i], bH);
                    mma16816(acc[i][j], ah[i], bL);
                }
        }

        __syncthreads();
        if (c < 15) {
            *(uint4*)&Ah_s[rA * SA + qA]     = pAh0;
            *(uint4*)&Ah_s[rA * SA + qA + 8] = pAh1;
            *(uint4*)&Al_s[rA * SA + qA]     = pAl0;
            *(uint4*)&Al_s[rA * SA + qA + 8] = pAl1;
            *(uint4*)&Xh_s[mX * SX + cX]     = pXh;
            *(uint4*)&Xl_s[mX * SX + cX]     = pXl;
        }
        __syncthreads();
    }

    // --- epilogue: write xg1 and xg2 = d2*xg1 - x as bf16 hi/lo ---
    const size_t obase = (size_t)bt * N_ * CI_;
#pragma unroll
    for (int i = 0; i < 2; i++) {
        const int row = n0 + wm + i * 16 + (lane >> 2);
        const float d2a = g_diag2[t * N_ + row];
        const float d2b = g_diag2[t * N_ + row + 8];
#pragma unroll
        for (int j = 0; j < 4; j++) {
            const int col = wn + j * 8 + (lane & 3) * 2;
#pragma unroll
            for (int rr = 0; rr < 2; rr++) {
                const int r = row + rr * 8;
                const float d2 = rr ? d2b : d2a;
                const float v0 = acc[i][j][rr * 2 + 0];
                const float v1 = acc[i][j][rr * 2 + 1];
                const size_t idx = obase + (size_t)r * CI_ + col;
                // reconstruct x = xh + xl
                const __nv_bfloat162 xh2 = *(const __nv_bfloat162*)(g_xh + idx);
                const __nv_bfloat162 xl2 = *(const __nv_bfloat162*)(g_xl + idx);
                const float x0 = __bfloat162float(xh2.x) + __bfloat162float(xl2.x);
                const float x1 = __bfloat162float(xh2.y) + __bfloat162float(xl2.y);
                const float w0 = fmaf(d2, v0, -x0);
                const float w1 = fmaf(d2, v1, -x1);
                // split xg1
                const __nv_bfloat16 h0 = __float2bfloat16(v0);
                const __nv_bfloat16 h1 = __float2bfloat16(v1);
                *(__nv_bfloat162*)(g_x1h + idx) = __halves2bfloat162(h0, h1);
                *(__nv_bfloat162*)(g_x1l + idx) = __halves2bfloat162(
                    __float2bfloat16(v0 - __bfloat162float(h0)),
                    __float2bfloat16(v1 - __bfloat162float(h1)));
                // split xg2
                const __nv_bfloat16 g0 = __float2bfloat16(w0);
                const __nv_bfloat16 g1 = __float2bfloat16(w1);
                *(__nv_bfloat162*)(g_x2h + idx) = __halves2bfloat162(g0, g1);
                *(__nv_bfloat162*)(g_x2l + idx) = __halves2bfloat162(
                    __float2bfloat16(w0 - __bfloat162float(g0)),
                    __float2bfloat16(w1 - __bfloat162float(g1)));
            }
        }
    }
}

// ---------------------------------------------------------------------------
// Kernel 3: fused theta-gen + output contraction on TENSOR CORES.
// theta-gen is the round-12 form (coalesced scalar W loads -- round-13's
// float2 restructure regressed via L2 sector locality and was reverted).
// xg staging is now a pure bf16 copy from the precomputed hi/lo arrays.
// ---------------------------------------------------------------------------
#define STH 72   // theta row stride (bf16): 64 + 8
#define SXG 24   // xg row stride (bf16): 16 + 8
#define KOUT_BF16  (2 * 8 * 16 * STH + 2 * 8 * 32 * SXG)
#define KOUT_BYTES (KOUT_BF16 * 2 + (512 + 96 + 8) * 4)

__global__ void __launch_bounds__(256, 2) k_out(const float* __restrict__ emb,
                                                const float* __restrict__ W,
                                                const float* __restrict__ bp,
                                                float* __restrict__ out) {
    extern __shared__ __align__(16) char smraw[];
    __nv_bfloat16* thh = (__nv_bfloat16*)smraw;        // 8*16*STH
    __nv_bfloat16* thl = thh + 8 * 16 * STH;
    __nv_bfloat16* xgh = thl + 8 * 16 * STH;           // 8*32*SXG
    __nv_bfloat16* xgl = xgh + 8 * 32 * SXG;
    float* bias_s = (float*)(xgl + 8 * 32 * SXG);      // 512
    float* emb_s  = bias_s + 512;                      // 80 (pad 96)

    const int t  = blockIdx.y;
    const int n0 = blockIdx.x * 8;
    const int tid = threadIdx.x;

    if (tid < 8 * E_)
        emb_s[tid] = emb[((size_t)t * N_ + n0 + tid / E_) * E_ + (tid % E_)];
    __syncthreads();

    for (int ii = tid; ii < 8 * CO_; ii += 256) {
        const int nl = ii >> 6;
        const int o  = ii & 63;
        float v = 0.f;
#pragma unroll
        for (int d = 0; d < E_; d++)
            v = fmaf(emb_s[nl * E_ + d], bp[((size_t)t * E_ + d) * CO_ + o], v);
        bias_s[ii] = v;
    }

    const int lane = tid & 31;
    const int g    = tid >> 5;          // node within tile (= warp)

    const int lnl = tid >> 5;
    const int lb  = tid & 31;           // staging: thread = (node lnl, batch lb)
    const size_t xgbase = (((size_t)lb * T_ + t) * N_ + n0 + lnl) * CI_;

    // theta-gen slot (round-12 form): 4 slots of (kic, o), stride 256
    const int kic0 = tid >> 6;          // slot r: kic = kic0 + r*4
    const int oo   = tid & 63;

    // ldmatrix per-lane sub-tile offsets (same mapping as k_spmm)
    const int sub = lane >> 3;
    const int rl  = lane & 7;
    const int rAdd = ((sub & 1) << 3) + rl;
    const int cAdd = (sub >> 1) << 3;
    const unsigned baseTh = sptr(thh);
    const unsigned baseTl = sptr(thl);
    const unsigned baseXh = sptr(xgh);
    const unsigned baseXl = sptr(xgl);

    float acc[2][8][4];
#pragma unroll
    for (int i = 0; i < 2; i++)
#pragma unroll
        for (int j = 0; j < 8; j++)
#pragma unroll
            for (int r = 0; r < 4; r++) acc[i][j][r] = 0.f;

    for (int c = 0; c < 12; c++) {
        const int k  = c >> 2;
        const int i0 = (c & 3) * 16;
        __syncthreads();

        // --- stage xg chunk: pure bf16 hi/lo copy from global ---
        {
            const __nv_bfloat16* sh;
            const __nv_bfloat16* sl;
            if (k == 0)      { sh = g_xh;  sl = g_xl;  }
            else if (k == 1) { sh = g_x1h; sl = g_x1l; }
            else             { sh = g_x2h; sl = g_x2l; }
            const uint4 h0 = *(const uint4*)(sh + xgbase + i0);
            const uint4 h1 = *(const uint4*)(sh + xgbase + i0 + 8);
            const uint4 l0 = *(const uint4*)(sl + xgbase + i0);
            const uint4 l1 = *(const uint4*)(sl + xgbase + i0 + 8);
            __nv_bfloat16* xh_row = xgh + (lnl * 32 + lb) * SXG;
            __nv_bfloat16* xl_row = xgl + (lnl * 32 + lb) * SXG;
            *(uint4*)&xh_row[0] = h0;
            *(uint4*)&xh_row[8] = h1;
            *(uint4*)&xl_row[0] = l0;
            *(uint4*)&xl_row[8] = l1;
        }

        // --- theta-gen (round-12 form): register-blocked over the 8 nodes ---
        // W index: (((t*E + d)*K + k)*CI + i)*CO + o ; d-stride = K*CI*CO
        const float* wbase = W + (((size_t)t * E_ * K_ + k) * CI_ + i0) * CO_;
#pragma unroll 1
        for (int r = 0; r < 4; r++) {
            const int kic = kic0 + r * 4;
            const float* wp = wbase + kic * CO_ + oo;
            float th[8];
#pragma unroll
            for (int nl = 0; nl < 8; nl++) th[nl] = 0.f;
#pragma unroll
            for (int d = 0; d < E_; d++) {
                const float wv = wp[(size_t)d * (K_ * CI_ * CO_)];
#pragma unroll
                for (int nl = 0; nl < 8; nl++)
                    th[nl] = fmaf(emb_s[nl * E_ + d], wv, th[nl]);
            }
#pragma unroll
            for (int nl = 0; nl < 8; nl++) {
                const __nv_bfloat16 h = __float2bfloat16(th[nl]);
                thh[(nl * 16 + kic) * STH + oo] = h;
                thl[(nl * 16 + kic) * STH + oo] =
                    __float2bfloat16(th[nl] - __bfloat162float(h));
            }
        }
        __syncthreads();

        // --- tensor-core contraction: per warp, 32x64x16 GEMM step ---
        {
            unsigned ah[2][4], al[2][4], bh[4][4], bl[4][4];
#pragma unroll
            for (int i = 0; i < 2; i++) {
                const unsigned off =
                    (unsigned)(((g * 32 + i * 16 + rAdd) * SXG + cAdd) * 2);
                ldsm4(ah[i], baseXh + off);
                ldsm4(al[i], baseXl + off);
            }
#pragma unroll
            for (int jp = 0; jp < 4; jp++) {
                const unsigned off =
                    (unsigned)(((g * 16 + rAdd) * STH + jp * 16 + cAdd) * 2);
                ldsm4t(bh[jp], baseTh + off);
                ldsm4t(bl[jp], baseTl + off);
            }
#pragma unroll
            for (int i = 0; i < 2; i++)
#pragma unroll
                for (int j = 0; j < 8; j++) {
                    const unsigned* bH = &bh[j >> 1][(j & 1) * 2];
                    const unsigned* bL = &bl[j >> 1][(j & 1) * 2];
                    mma16816(acc[i][j], ah[i], bH);   // xh*th
                    mma16816(acc[i][j], al[i], bH);   // xl*th
                    mma16816(acc[i][j], ah[i], bL);   // xh*tl
                }
        }
    }

    // --- epilogue: relu(acc + bias) -> out[b,t,n,o] from c-fragments ---
    const int n = n0 + g;
#pragma unroll
    for (int j = 0; j < 8; j++) {
        const int col = j * 8 + (lane & 3) * 2;
        const float b0 = bias_s[g * 64 + col];
        const float b1 = bias_s[g * 64 + col + 1];
#pragma unroll
        for (int i = 0; i < 2; i++) {
            const int row0 = i * 16 + (lane >> 2);
            const int row1 = row0 + 8;
            float2 lo, hi;
            lo.x = fmaxf(acc[i][j][0] + b0, 0.f);
            lo.y = fmaxf(acc[i][j][1] + b1, 0.f);
            hi.x = fmaxf(acc[i][j][2] + b0, 0.f);
            hi.y = fmaxf(acc[i][j][3] + b1, 0.f);
            *(float2*)(out + (((size_t)row0 * T_ + t) * N_ + n) * CO_ + col) = lo;
            *(float2*)(out + (((size_t)row1 * T_ + t) * N_ + n) * CO_ + col) = hi;
        }
    }
}

extern "C" void kernel_launch(void* const* d_in, const int* in_sizes, int n_in,
                              void* d_out, int out_size) {
    const float* x   = (const float*)d_in[0];  // [B,T,N,Ci]
    const float* emb = (const float*)d_in[1];  // [T,N,E]
    const float* W   = (const float*)d_in[2];  // [T,E,K,Ci,Co]
    const float* bp  = (const float*)d_in[3];  // [T,E,Co]
    float* out = (float*)d_out;                // [B,T,N,Co]

    cudaFuncSetAttribute(k_out, cudaFuncAttributeMaxDynamicSharedMemorySize,
                         KOUT_BYTES);

    k_adj<<<dim3(N_ / 8, T_), 256>>>(emb);
    k_split<<<(B_ * T_ * N_ * CI_) / (256 * 4), 256>>>(x);
    k_spmm<<<dim3(N_ / 128, B_ * T_), 256>>>();
    k_out<<<dim3(N_ / 8, T_), 256, KOUT_BYTES>>>(emb, W, bp, out);
}

// round 17
// speedup vs baseline: 1.0533x; 1.0434x over previous
#include <cuda_runtime.h>
#include <cuda_bf16.h>
#include <cstdint>

#define B_  32
#define T_  12
#define N_  512
#define E_  10
#define K_  3
#define CI_ 64
#define CO_ 64

// Scratch (static device globals -- allocation-free per harness rules)
__device__ float         g_diag2[T_ * N_];                    // 2 * diag(A), fp32
__device__ __nv_bfloat16 g_Ah[(size_t)T_ * N_ * N_];          // A hi (bf16)
__device__ __nv_bfloat16 g_Al[(size_t)T_ * N_ * N_];          // A lo (bf16)
__device__ __nv_bfloat16 g_xh[(size_t)B_ * T_ * N_ * CI_];    // x hi
__device__ __nv_bfloat16 g_xl[(size_t)B_ * T_ * N_ * CI_];    // x lo
__device__ __nv_bfloat16 g_x1h[(size_t)B_ * T_ * N_ * CI_];   // xg1 hi
__device__ __nv_bfloat16 g_x1l[(size_t)B_ * T_ * N_ * CI_];   // xg1 lo
__device__ __nv_bfloat16 g_x2h[(size_t)B_ * T_ * N_ * CI_];   // xg2 hi
__device__ __nv_bfloat16 g_x2l[(size_t)B_ * T_ * N_ * CI_];   // xg2 lo

// ---------------------------------------------------------------------------
// Kernel 1: adjacency. Warp-per-row; block = 8 rows, emb[t] loaded once.
// ---------------------------------------------------------------------------
__global__ void __launch_bounds__(256) k_adj(const float* __restrict__ emb) {
    const int t    = blockIdx.y;
    const int wid  = threadIdx.x >> 5;
    const int lane = threadIdx.x & 31;
    const int n    = blockIdx.x * 8 + wid;

    __shared__ float se[N_ * E_];
    const float* et = emb + (size_t)t * N_ * E_;
    for (int i = threadIdx.x; i < N_ * E_; i += 256) se[i] = et[i];
    __syncthreads();

    float en[E_];
#pragma unroll
    for (int e = 0; e < E_; e++) en[e] = se[n * E_ + e];

    float v[16];
#pragma unroll
    for (int q = 0; q < 16; q++) {
        const int m = lane + 32 * q;
        float s = 0.f;
#pragma unroll
        for (int e = 0; e < E_; e++) s = fmaf(en[e], se[m * E_ + e], s);
        v[q] = fmaxf(s, 0.f);
    }

    float mx = v[0];
#pragma unroll
    for (int q = 1; q < 16; q++) mx = fmaxf(mx, v[q]);
#pragma unroll
    for (int o = 16; o > 0; o >>= 1) mx = fmaxf(mx, __shfl_xor_sync(0xffffffffu, mx, o));

    float sum = 0.f;
#pragma unroll
    for (int q = 0; q < 16; q++) {
        v[q] = expf(v[q] - mx);
        sum += v[q];
    }
#pragma unroll
    for (int o = 16; o > 0; o >>= 1) sum += __shfl_xor_sync(0xffffffffu, sum, o);
    const float inv = 1.0f / sum;

    const size_t base = ((size_t)t * N_ + n) * N_;
#pragma unroll
    for (int q = 0; q < 16; q++) {
        const float p = v[q] * inv;
        const __nv_bfloat16 h = __float2bfloat16(p);
        const __nv_bfloat16 l = __float2bfloat16(p - __bfloat162float(h));
        g_Ah[base + lane + 32 * q] = h;
        g_Al[base + lane + 32 * q] = l;
        if (q == (n >> 5) && lane == (n & 31))
            g_diag2[t * N_ + n] = 2.0f * p;
    }
}

// ---------------------------------------------------------------------------
// Kernel 1b: split x into bf16 hi/lo. 4 elems/thread, exact-size grid.
// ---------------------------------------------------------------------------
__global__ void __launch_bounds__(256) k_split(const float* __restrict__ x) {
    const size_t i = ((size_t)blockIdx.x * 256 + threadIdx.x) * 4;
    const float4 vv = *(const float4*)(x + i);
    float f[4];
    f[0] = vv.x; f[1] = vv.y; f[2] = vv.z; f[3] = vv.w;
    __nv_bfloat16 h[4], l[4];
#pragma unroll
    for (int j = 0; j < 4; j++) {
        h[j] = __float2bfloat16(f[j]);
        l[j] = __float2bfloat16(f[j] - __bfloat162float(h[j]));
    }
    *((__nv_bfloat162*)(g_xh + i))     = __halves2bfloat162(h[0], h[1]);
    *((__nv_bfloat162*)(g_xh + i + 2)) = __halves2bfloat162(h[2], h[3]);
    *((__nv_bfloat162*)(g_xl + i))     = __halves2bfloat162(l[0], l[1]);
    *((__nv_bfloat162*)(g_xl + i + 2)) = __halves2bfloat162(l[2], l[3]);
}

// ---------------------------------------------------------------------------
// mma helpers (shared by k_spmm and k_out)
// ---------------------------------------------------------------------------
__device__ __forceinline__ unsigned sptr(const void* p) {
    return (unsigned)__cvta_generic_to_shared(p);
}
__device__ __forceinline__ void ldsm4(unsigned* r, unsigned a) {
    asm volatile("ldmatrix.sync.aligned.m8n8.x4.shared.b16 {%0,%1,%2,%3}, [%4];"
                 : "=r"(r[0]), "=r"(r[1]), "=r"(r[2]), "=r"(r[3]) : "r"(a));
}
__device__ __forceinline__ void ldsm4t(unsigned* r, unsigned a) {
    asm volatile("ldmatrix.sync.aligned.m8n8.x4.trans.shared.b16 {%0,%1,%2,%3}, [%4];"
                 : "=r"(r[0]), "=r"(r[1]), "=r"(r[2]), "=r"(r[3]) : "r"(a));
}
__device__ __forceinline__ void mma16816(float* c, const unsigned* a, const unsigned* b) {
    asm volatile(
        "mma.sync.aligned.m16n8k16.row.col.f32.bf16.bf16.f32 "
        "{%0,%1,%2,%3}, {%4,%5,%6,%7}, {%8,%9}, {%0,%1,%2,%3};"
        : "+f"(c[0]), "+f"(c[1]), "+f"(c[2]), "+f"(c[3])
        : "r"(a[0]), "r"(a[1]), "r"(a[2]), "r"(a[3]), "r"(b[0]), "r"(b[1]));
}

// ---------------------------------------------------------------------------
// Kernel 2: xg1 = A @ x via mma.sync m16n8k16 bf16, 3-product split.
// Epilogue: fragments staged through SMEM, then ROW-COALESCED uint4 stores of
// xg1 and xg2 = d2*xg1 - x as bf16 hi/lo. (Round-15's fragment-order scatter
// stores cost ~45us; coalescing is load-bearing.)
// ---------------------------------------------------------------------------
#define SA 40   // Ah_s row stride (bf16)
#define SX 72   // Xs row stride (bf16)

__global__ void __launch_bounds__(256) k_spmm() {
    const int bt = blockIdx.y;             // b*T + t
    const int t  = bt % T_;
    const int n0 = blockIdx.x * 128;

    __shared__ __align__(16) __nv_bfloat16 Ah_s[128 * SA];
    __shared__ __align__(16) __nv_bfloat16 Al_s[128 * SA];
    __shared__ __align__(16) __nv_bfloat16 Xh_s[32 * SX];
    __shared__ __align__(16) __nv_bfloat16 Xl_s[32 * SX];
    __shared__ __align__(16) float St[64 * 68];   // epilogue staging (17KB)

    const int tid  = threadIdx.x;
    const int lane = tid & 31;
    const int warp = tid >> 5;
    const int wm   = (warp & 3) * 32;
    const int wn   = (warp >> 2) * 32;

    const int rA = tid >> 1;
    const int qA = (tid & 1) * 16;
    const int mX = tid >> 3;
    const int cX = (tid & 7) * 8;

    const __nv_bfloat16* gAh = g_Ah + ((size_t)t * N_ + n0 + rA) * N_;
    const __nv_bfloat16* gAl = g_Al + ((size_t)t * N_ + n0 + rA) * N_;
    const __nv_bfloat16* gXh = g_xh + ((size_t)bt * N_ + mX) * CI_ + cX;
    const __nv_bfloat16* gXl = g_xl + ((size_t)bt * N_ + mX) * CI_ + cX;

    float acc[2][4][4];
#pragma unroll
    for (int i = 0; i < 2; i++)
#pragma unroll
        for (int j = 0; j < 4; j++)
#pragma unroll
            for (int r = 0; r < 4; r++) acc[i][j][r] = 0.f;

    const int sub = lane >> 3;
    const int rl  = lane & 7;
    const int rAdd = ((sub & 1) << 3) + rl;
    const int cAdd = (sub >> 1) << 3;
    const unsigned baseAh = sptr(Ah_s);
    const unsigned baseAl = sptr(Al_s);
    const unsigned baseXh = sptr(Xh_s);
    const unsigned baseXl = sptr(Xl_s);

    uint4 pAh0, pAh1, pAl0, pAl1, pXh, pXl;

    pAh0 = *(const uint4*)(gAh + qA);
    pAh1 = *(const uint4*)(gAh + qA + 8);
    pAl0 = *(const uint4*)(gAl + qA);
    pAl1 = *(const uint4*)(gAl + qA + 8);
    pXh  = *(const uint4*)(gXh);
    pXl  = *(const uint4*)(gXl);
    *(uint4*)&Ah_s[rA * SA + qA]     = pAh0;
    *(uint4*)&Ah_s[rA * SA + qA + 8] = pAh1;
    *(uint4*)&Al_s[rA * SA + qA]     = pAl0;
    *(uint4*)&Al_s[rA * SA + qA + 8] = pAl1;
    *(uint4*)&Xh_s[mX * SX + cX]     = pXh;
    *(uint4*)&Xl_s[mX * SX + cX]     = pXl;
    __syncthreads();

    for (int c = 0; c < 16; c++) {
        if (c < 15) {
            const int m0 = (c + 1) * 32;
            pAh0 = *(const uint4*)(gAh + m0 + qA);
            pAh1 = *(const uint4*)(gAh + m0 + qA + 8);
            pAl0 = *(const uint4*)(gAl + m0 + qA);
            pAl1 = *(const uint4*)(gAl + m0 + qA + 8);
            pXh  = *(const uint4*)(gXh + (size_t)m0 * CI_);
            pXl  = *(const uint4*)(gXl + (size_t)m0 * CI_);
        }

#pragma unroll
        for (int s = 0; s < 2; s++) {
            unsigned ah[2][4], al[2][4], bh[2][4], bl[2][4];
#pragma unroll
            for (int i = 0; i < 2; i++) {
                const unsigned off =
                    (unsigned)(((wm + i * 16 + rAdd) * SA + s * 16 + cAdd) * 2);
                ldsm4(ah[i], baseAh + off);
                ldsm4(al[i], baseAl + off);
            }
#pragma unroll
            for (int jp = 0; jp < 2; jp++) {
                const unsigned off =
                    (unsigned)(((s * 16 + rAdd) * SX + wn + jp * 16 + cAdd) * 2);
                ldsm4t(bh[jp], baseXh + off);
                ldsm4t(bl[jp], baseXl + off);
            }
#pragma unroll
            for (int i = 0; i < 2; i++)
#pragma unroll
                for (int j = 0; j < 4; j++) {
                    const unsigned* bH = &bh[j >> 1][(j & 1) * 2];
                    const unsigned* bL = &bl[j >> 1][(j & 1) * 2];
                    mma16816(acc[i][j], ah[i], bH);
                    mma16816(acc[i][j], al[i], bH);
                    mma16816(acc[i][j], ah[i], bL);
                }
        }

        __syncthreads();
        if (c < 15) {
            *(uint4*)&Ah_s[rA * SA + qA]     = pAh0;
            *(uint4*)&Ah_s[rA * SA + qA + 8] = pAh1;
            *(uint4*)&Al_s[rA * SA + qA]     = pAl0;
            *(uint4*)&Al_s[rA * SA + qA + 8] = pAl1;
            *(uint4*)&Xh_s[mX * SX + cX]     = pXh;
            *(uint4*)&Xl_s[mX * SX + cX]     = pXl;
        }
        __syncthreads();
    }

    // --- epilogue: stage fragments in SMEM, then coalesced global stores ---
    const size_t obase = (size_t)bt * N_ * CI_;
    const int hsel = (warp & 3) >> 1;    // half owning this warp's rows
    const int r64  = wm & 63;            // row base within half
    const int rowo = tid >> 2;           // output row within half (0..63)
    const int c0   = (tid & 3) * 16;     // output col base (16 cols/thread)

    for (int h = 0; h < 2; h++) {
        __syncthreads();
        if (hsel == h) {
#pragma unroll
            for (int i = 0; i < 2; i++)
#pragma unroll
                for (int j = 0; j < 4; j++) {
                    const int r  = r64 + i * 16 + (lane >> 2);
                    const int cb = wn + j * 8 + (lane & 3) * 2;
                    float2 lo, hi;
                    lo.x = acc[i][j][0]; lo.y = acc[i][j][1];
                    hi.x = acc[i][j][2]; hi.y = acc[i][j][3];
                    *(float2*)&St[r * 68 + cb]       = lo;
                    *(float2*)&St[(r + 8) * 68 + cb] = hi;
                }
        }
        __syncthreads();
        {
            const int grow = n0 + h * 64 + rowo;
            const float d2 = g_diag2[t * N_ + grow];
            const size_t idx = obase + (size_t)grow * CI_ + c0;

            float v[16];
#pragma unroll
            for (int q = 0; q < 4; q++) {
                const float4 f = *(const float4*)&St[rowo * 68 + c0 + q * 4];
                v[q * 4 + 0] = f.x; v[q * 4 + 1] = f.y;
                v[q * 4 + 2] = f.z; v[q * 4 + 3] = f.w;
            }
            // reconstruct x = xh + xl (coalesced uint4 loads)
            float xv[16];
            {
                const uint4 xh0 = *(const uint4*)(g_xh + idx);
                const uint4 xh1 = *(const uint4*)(g_xh + idx + 8);
                const uint4 xl0 = *(const uint4*)(g_xl + idx);
                const uint4 xl1 = *(const uint4*)(g_xl + idx + 8);
                const __nv_bfloat162* ph0 = (const __nv_bfloat162*)&xh0;
                const __nv_bfloat162* ph1 = (const __nv_bfloat162*)&xh1;
                const __nv_bfloat162* pl0 = (const __nv_bfloat162*)&xl0;
                const __nv_bfloat162* pl1 = (const __nv_bfloat162*)&xl1;
#pragma unroll
                for (int q = 0; q < 4; q++) {
                    xv[q * 2 + 0] = __bfloat162float(ph0[q].x) + __bfloat162float(pl0[q].x);
                    xv[q * 2 + 1] = __bfloat162float(ph0[q].y) + __bfloat162float(pl0[q].y);
                    xv[8 + q * 2 + 0] = __bfloat162float(ph1[q].x) + __bfloat162float(pl1[q].x);
                    xv[8 + q * 2 + 1] = __bfloat162float(ph1[q].y) + __bfloat162float(pl1[q].y);
                }
            }
            // split xg1 and xg2, write 4 arrays with uint4 stores
            __align__(16) __nv_bfloat16 b1h[16], b1l[16], b2h[16], b2l[16];
#pragma unroll
            for (int e2 = 0; e2 < 16; e2++) {
                const float v1 = v[e2];
                const float w  = fmaf(d2, v1, -xv[e2]);
                const __nv_bfloat16 h1b = __float2bfloat16(v1);
                b1h[e2] = h1b;
                b1l[e2] = __float2bfloat16(v1 - __bfloat162float(h1b));
                const __nv_bfloat16 h2b = __float2bfloat16(w);
                b2h[e2] = h2b;
                b2l[e2] = __float2bfloat16(w - __bfloat162float(h2b));
            }
            *(uint4*)(g_x1h + idx)     = *(const uint4*)&b1h[0];
            *(uint4*)(g_x1h + idx + 8) = *(const uint4*)&b1h[8];
            *(uint4*)(g_x1l + idx)     = *(const uint4*)&b1l[0];
            *(uint4*)(g_x1l + idx + 8) = *(const uint4*)&b1l[8];
            *(uint4*)(g_x2h + idx)     = *(const uint4*)&b2h[0];
            *(uint4*)(g_x2h + idx + 8) = *(const uint4*)&b2h[8];
            *(uint4*)(g_x2l + idx)     = *(const uint4*)&b2l[0];
            *(uint4*)(g_x2l + idx + 8) = *(const uint4*)&b2l[8];
        }
    }
}

// ---------------------------------------------------------------------------
// Kernel 3: fused theta-gen + output contraction on TENSOR CORES.
// (verbatim round-15 version -- measured 204.6us)
// ---------------------------------------------------------------------------
#define STH 72   // theta row stride (bf16): 64 + 8
#define SXG 24   // xg row stride (bf16): 16 + 8
#define KOUT_BF16  (2 * 8 * 16 * STH + 2 * 8 * 32 * SXG)
#define KOUT_BYTES (KOUT_BF16 * 2 + (512 + 96 + 8) * 4)

__global__ void __launch_bounds__(256, 2) k_out(const float* __restrict__ emb,
                                                const float* __restrict__ W,
                                                const float* __restrict__ bp,
                                                float* __restrict__ out) {
    extern __shared__ __align__(16) char smraw[];
    __nv_bfloat16* thh = (__nv_bfloat16*)smraw;        // 8*16*STH
    __nv_bfloat16* thl = thh + 8 * 16 * STH;
    __nv_bfloat16* xgh = thl + 8 * 16 * STH;           // 8*32*SXG
    __nv_bfloat16* xgl = xgh + 8 * 32 * SXG;
    float* bias_s = (float*)(xgl + 8 * 32 * SXG);      // 512
    float* emb_s  = bias_s + 512;                      // 80 (pad 96)

    const int t  = blockIdx.y;
    const int n0 = blockIdx.x * 8;
    const int tid = threadIdx.x;

    if (tid < 8 * E_)
        emb_s[tid] = emb[((size_t)t * N_ + n0 + tid / E_) * E_ + (tid % E_)];
    __syncthreads();

    for (int ii = tid; ii < 8 * CO_; ii += 256) {
        const int nl = ii >> 6;
        const int o  = ii & 63;
        float v = 0.f;
#pragma unroll
        for (int d = 0; d < E_; d++)
            v = fmaf(emb_s[nl * E_ + d], bp[((size_t)t * E_ + d) * CO_ + o], v);
        bias_s[ii] = v;
    }

    const int lane = tid & 31;
    const int g    = tid >> 5;          // node within tile (= warp)

    const int lnl = tid >> 5;
    const int lb  = tid & 31;           // staging: thread = (node lnl, batch lb)
    const size_t xgbase = (((size_t)lb * T_ + t) * N_ + n0 + lnl) * CI_;

    // theta-gen slot (round-12 form): 4 slots of (kic, o), stride 256
    const int kic0 = tid >> 6;          // slot r: kic = kic0 + r*4
    const int oo   = tid & 63;

    // ldmatrix per-lane sub-tile offsets (same mapping as k_spmm)
    const int sub = lane >> 3;
    const int rl  = lane & 7;
    const int rAdd = ((sub & 1) << 3) + rl;
    const int cAdd = (sub >> 1) << 3;
    const unsigned baseTh = sptr(thh);
    const unsigned baseTl = sptr(thl);
    const unsigned baseXh = sptr(xgh);
    const unsigned baseXl = sptr(xgl);

    float acc[2][8][4];
#pragma unroll
    for (int i = 0; i < 2; i++)
#pragma unroll
        for (int j = 0; j < 8; j++)
#pragma unroll
            for (int r = 0; r < 4; r++) acc[i][j][r] = 0.f;

    for (int c = 0; c < 12; c++) {
        const int k  = c >> 2;
        const int i0 = (c & 3) * 16;
        __syncthreads();

        // --- stage xg chunk: pure bf16 hi/lo copy from global ---
        {
            const __nv_bfloat16* sh;
            const __nv_bfloat16* sl;
            if (k == 0)      { sh = g_xh;  sl = g_xl;  }
            else if (k == 1) { sh = g_x1h; sl = g_x1l; }
            else             { sh = g_x2h; sl = g_x2l; }
            const uint4 h0 = *(const uint4*)(sh + xgbase + i0);
            const uint4 h1 = *(const uint4*)(sh + xgbase + i0 + 8);
            const uint4 l0 = *(const uint4*)(sl + xgbase + i0);
            const uint4 l1 = *(const uint4*)(sl + xgbase + i0 + 8);
            __nv_bfloat16* xh_row = xgh + (lnl * 32 + lb) * SXG;
            __nv_bfloat16* xl_row = xgl + (lnl * 32 + lb) * SXG;
            *(uint4*)&xh_row[0] = h0;
            *(uint4*)&xh_row[8] = h1;
            *(uint4*)&xl_row[0] = l0;
            *(uint4*)&xl_row[8] = l1;
        }

        // --- theta-gen (round-12 form): register-blocked over the 8 nodes ---
        const float* wbase = W + (((size_t)t * E_ * K_ + k) * CI_ + i0) * CO_;
#pragma unroll 1
        for (int r = 0; r < 4; r++) {
            const int kic = kic0 + r * 4;
            const float* wp = wbase + kic * CO_ + oo;
            float th[8];
#pragma unroll
            for (int nl = 0; nl < 8; nl++) th[nl] = 0.f;
#pragma unroll
            for (int d = 0; d < E_; d++) {
                const float wv = wp[(size_t)d * (K_ * CI_ * CO_)];
#pragma unroll
                for (int nl = 0; nl < 8; nl++)
                    th[nl] = fmaf(emb_s[nl * E_ + d], wv, th[nl]);
            }
#pragma unroll
            for (int nl = 0; nl < 8; nl++) {
                const __nv_bfloat16 h = __float2bfloat16(th[nl]);
                thh[(nl * 16 + kic) * STH + oo] = h;
                thl[(nl * 16 + kic) * STH + oo] =
                    __float2bfloat16(th[nl] - __bfloat162float(h));
            }
        }
        __syncthreads();

        // --- tensor-core contraction: per warp, 32x64x16 GEMM step ---
        {
            unsigned ah[2][4], al[2][4], bh[4][4], bl[4][4];
#pragma unroll
            for (int i = 0; i < 2; i++) {
                const unsigned off =
                    (unsigned)(((g * 32 + i * 16 + rAdd) * SXG + cAdd) * 2);
                ldsm4(ah[i], baseXh + off);
                ldsm4(al[i], baseXl + off);
            }
#pragma unroll
            for (int jp = 0; jp < 4; jp++) {
                const unsigned off =
                    (unsigned)(((g * 16 + rAdd) * STH + jp * 16 + cAdd) * 2);
                ldsm4t(bh[jp], baseTh + off);
                ldsm4t(bl[jp], baseTl + off);
            }
#pragma unroll
            for (int i = 0; i < 2; i++)
#pragma unroll
                for (int j = 0; j < 8; j++) {
                    const unsigned* bH = &bh[j >> 1][(j & 1) * 2];
                    const unsigned* bL = &bl[j >> 1][(j & 1) * 2];
                    mma16816(acc[i][j], ah[i], bH);   // xh*th
                    mma16816(acc[i][j], al[i], bH);   // xl*th
                    mma16816(acc[i][j], ah[i], bL);   // xh*tl
                }
        }
    }

    // --- epilogue: relu(acc + bias) -> out[b,t,n,o] from c-fragments ---
    const int n = n0 + g;
#pragma unroll
    for (int j = 0; j < 8; j++) {
        const int col = j * 8 + (lane & 3) * 2;
        const float b0 = bias_s[g * 64 + col];
        const float b1 = bias_s[g * 64 + col + 1];
#pragma unroll
        for (int i = 0; i < 2; i++) {
            const int row0 = i * 16 + (lane >> 2);
            const int row1 = row0 + 8;
            float2 lo, hi;
            lo.x = fmaxf(acc[i][j][0] + b0, 0.f);
            lo.y = fmaxf(acc[i][j][1] + b1, 0.f);
            hi.x = fmaxf(acc[i][j][2] + b0, 0.f);
            hi.y = fmaxf(acc[i][j][3] + b1, 0.f);
            *(float2*)(out + (((size_t)row0 * T_ + t) * N_ + n) * CO_ + col) = lo;
            *(float2*)(out + (((size_t)row1 * T_ + t) * N_ + n) * CO_ + col) = hi;
        }
    }
}

extern "C" void kernel_launch(void* const* d_in, const int* in_sizes, int n_in,
                              void* d_out, int out_size) {
    const float* x   = (const float*)d_in[0];  // [B,T,N,Ci]
    const float* emb = (const float*)d_in[1];  // [T,N,E]
    const float* W   = (const float*)d_in[2];  // [T,E,K,Ci,Co]
    const float* bp  = (const float*)d_in[3];  // [T,E,Co]
    float* out = (float*)d_out;                // [B,T,N,Co]

    cudaFuncSetAttribute(k_out, cudaFuncAttributeMaxDynamicSharedMemorySize,
                         KOUT_BYTES);

    k_adj<<<dim3(N_ / 8, T_), 256>>>(emb);
    k_split<<<(B_ * T_ * N_ * CI_) / (256 * 4), 256>>>(x);
    k_spmm<<<dim3(N_ / 128, B_ * T_), 256>>>();
    k_out<<<dim3(N_ / 8, T_), 256, KOUT_BYTES>>>(emb, W, bp, out);
}